// round 15
// baseline (speedup 1.0000x reference)
#include <cuda_runtime.h>

// ---------------- problem constants ----------------
#define BATCH   8
#define NPTS    4096
#define NCEN    1024
#define DFEAT   32
#define CIN     35        // 3 + D
#define K1      40        // padded K for layer-1 GEMM
#define OUTCH   640

typedef unsigned long long u64;

// ---------------- device scratch (no allocations allowed) ----------------
static __device__ float g_z1  [524288 * 128];       // 268 MB
static __device__ float g_part[2 * 4096 * 256];     // per-blockrow partial sums / sumsq
static __device__ float g_gmax[8192 * 256];         // per-(center,channel) group max
static __device__ float g_gmin[8192 * 256];         // per-(center,channel) group min
static __device__ float g_ab1 [512];
static __device__ float g_ab2 [512];
static __device__ int   g_idx0[BATCH * NCEN * 16];
static __device__ int   g_idx1[BATCH * NCEN * 32];
static __device__ int   g_idx2[BATCH * NCEN * 64];

// ---------------- packed f32x2 helpers ----------------
__device__ __forceinline__ u64 pack2(float x) {
    u64 d;
    asm("mov.b64 %0, {%1, %1};" : "=l"(d) : "f"(x));
    return d;
}
__device__ __forceinline__ void fma2(u64& c, u64 a, u64 b) {
    asm("fma.rn.f32x2 %0, %1, %2, %0;" : "+l"(c) : "l"(a), "l"(b));
}
__device__ __forceinline__ float2 unpack2(u64 d) {
    float2 f;
    asm("mov.b64 {%0, %1}, %2;" : "=f"(f.x), "=f"(f.y) : "l"(d));
    return f;
}

// ---------------- FPS: 512 threads, HW warp reductions, 1 bar/iter ----------------
__global__ void fps_kernel(const float* __restrict__ xyz, float* __restrict__ newxyz)
{
    int b   = blockIdx.x;
    int tid = threadIdx.x;                    // 512 threads
    const float* base = xyz + (size_t)b * NPTS * 3;

    float px[8], py[8], pz[8], dist[8];
#pragma unroll
    for (int u = 0; u < 8; u++) {
        int p = tid + u * 512;
        px[u] = base[p * 3 + 0];
        py[u] = base[p * 3 + 1];
        pz[u] = base[p * 3 + 2];
        dist[u] = 1e10f;
    }

    __shared__ unsigned s_vb[2][16];
    __shared__ unsigned s_ib[2][16];
    int lane = tid & 31, warp = tid >> 5;
    int far = 0;

    for (int t = 0; t < NCEN; t++) {
        float cx = base[far * 3 + 0];
        float cy = base[far * 3 + 1];
        float cz = base[far * 3 + 2];
        if (tid == 0) {
            float* o = newxyz + ((size_t)b * NCEN + t) * 3;
            o[0] = cx; o[1] = cy; o[2] = cz;
        }
        float bv = -1.0f; int bi = 0x7fffffff;
#pragma unroll
        for (int u = 0; u < 8; u++) {
            float dx = px[u] - cx, dy = py[u] - cy, dz = pz[u] - cz;
            float d  = dx * dx + dy * dy + dz * dz;
            float nd = fminf(dist[u], d);
            dist[u] = nd;
            int p = tid + u * 512;
            if (nd > bv || (nd == bv && p < bi)) { bv = nd; bi = p; }
        }
        // bv >= 0 always, so float bits compare as u32.
        int pb = t & 1;
        unsigned kb = __float_as_uint(bv);
        unsigned mx = __reduce_max_sync(0xffffffffu, kb);
        unsigned mi = __reduce_min_sync(0xffffffffu, (kb == mx) ? (unsigned)bi : 0xffffffffu);
        if (lane == 0) { s_vb[pb][warp] = mx; s_ib[pb][warp] = mi; }
        __syncthreads();
        // every warp redundantly reduces the 16 partials (no second barrier)
        unsigned v  = (lane < 16) ? s_vb[pb][lane] : 0u;
        unsigned ii = (lane < 16) ? s_ib[pb][lane] : 0xffffffffu;
        unsigned m2 = __reduce_max_sync(0xffffffffu, v);
        unsigned i2 = __reduce_min_sync(0xffffffffu, (v == m2) ? ii : 0xffffffffu);
        far = (int)i2;
    }
}

// ---------------- ball query: all 3 radii in one pass ----------------
__global__ void ballquery_kernel(const float* __restrict__ xyz,
                                 const float* __restrict__ newxyz,
                                 int* __restrict__ idx0,
                                 int* __restrict__ idx1,
                                 int* __restrict__ idx2)
{
    __shared__ float sx[NPTS], sy[NPTS], sz[NPTS];
    int b     = blockIdx.x >> 5;
    int cbase = (blockIdx.x & 31) * 32;
    const float* base = xyz + (size_t)b * NPTS * 3;

    for (int i = threadIdx.x; i < NPTS; i += 128) {
        sx[i] = base[i * 3 + 0];
        sy[i] = base[i * 3 + 1];
        sz[i] = base[i * 3 + 2];
    }
    __syncthreads();

    const float R0 = (float)(0.1 * 0.1);
    const float R1 = (float)(0.2 * 0.2);
    const float R2 = (float)(0.4 * 0.4);

    int warp = threadIdx.x >> 5, lane = threadIdx.x & 31;
    unsigned lmask = (1u << lane) - 1u;

    for (int ci = 0; ci < 8; ci++) {
        int s = cbase + warp * 8 + ci;
        const float* cen = newxyz + ((size_t)b * NCEN + s) * 3;
        float cx = cen[0], cy = cen[1], cz = cen[2];
        float cs2 = cx * cx + cy * cy + cz * cz;

        int n0 = 0, n1 = 0, n2 = 0;
        int f0 = 0, f1 = 0, f2 = 0;
        int* o0 = idx0 + ((size_t)b * NCEN + s) * 16;
        int* o1 = idx1 + ((size_t)b * NCEN + s) * 32;
        int* o2 = idx2 + ((size_t)b * NCEN + s) * 64;

        for (int bp = 0; bp < NPTS; bp += 32) {
            int p = bp + lane;
            float x = sx[p], y = sy[p], z = sz[p];
            float p2  = x * x + y * y + z * z;
            float dot = cx * x + cy * y + cz * z;
            float d   = (cs2 + p2) - 2.0f * dot;

            bool i2 = d <= R2;
            bool i1 = d <= R1;
            bool i0 = d <= R0;
            unsigned m0 = __ballot_sync(0xffffffffu, i0);
            unsigned m1 = __ballot_sync(0xffffffffu, i1);
            unsigned m2 = __ballot_sync(0xffffffffu, i2);

            if (n0 < 16) {
                if (i0) { int pos = n0 + __popc(m0 & lmask); if (pos < 16) o0[pos] = p; }
                if (n0 == 0 && m0) f0 = bp + __ffs(m0) - 1;
                n0 = min(16, n0 + __popc(m0));
            }
            if (n1 < 32) {
                if (i1) { int pos = n1 + __popc(m1 & lmask); if (pos < 32) o1[pos] = p; }
                if (n1 == 0 && m1) f1 = bp + __ffs(m1) - 1;
                n1 = min(32, n1 + __popc(m1));
            }
            if (n2 < 64) {
                if (i2) { int pos = n2 + __popc(m2 & lmask); if (pos < 64) o2[pos] = p; }
                if (n2 == 0 && m2) f2 = bp + __ffs(m2) - 1;
                n2 = min(64, n2 + __popc(m2));
            }
            if (n0 == 16 && n1 == 32 && n2 == 64) break;
        }
        for (int i = n0 + lane; i < 16; i += 32) o0[i] = f0;
        for (int i = n1 + lane; i < 32; i += 32) o1[i] = f1;
        for (int i = n2 + lane; i < 64; i += 32) o2[i] = f2;
    }
}

// ---------------- GEMM1: fused gather + (feat @ W1 + b1) + partial BN stats, f32x2 ----------------
template <int BN>
__global__ void __launch_bounds__(256)
gemm1_kernel(const float* __restrict__ xyz,
             const float* __restrict__ points,
             const int*   __restrict__ idx,
             const float* __restrict__ newxyz,
             const float* __restrict__ w,     // 35 x BN
             const float* __restrict__ bias,  // BN
             int Ksz,
             float* __restrict__ z1,          // M x BN
             float* __restrict__ partS,
             float* __restrict__ partQ)
{
    constexpr int NCF = BN / 64;
    constexpr int NP  = NCF * 2;
    __shared__ float As[K1 * 132];           // 5280 floats
    __shared__ float Ws[K1 * BN];

    int tid  = threadIdx.x;
    int by   = blockIdx.x;
    int m0   = by * 128;
    int warp = tid >> 5, lane = tid & 31;

    for (int r = warp; r < 128; r += 8) {
        int m  = m0 + r;
        int i  = idx[m];
        int bs = m / Ksz;
        int b  = bs >> 10;
        const float* px = xyz    + ((size_t)b * NPTS + i) * 3;
        const float* pf = points + ((size_t)b * NPTS + i) * DFEAT;
        const float* cn = newxyz + (size_t)bs * 3;
        float v = (lane < 3) ? (px[lane] - cn[lane]) : pf[lane - 3];
        As[lane * 132 + r] = v;
        if (lane < 8) {
            int k2 = lane + 32;
            As[k2 * 132 + r] = (k2 < CIN) ? pf[k2 - 3] : 0.0f;
        }
    }
    for (int j = tid; j < K1 * BN; j += 256) {
        int kk = j / BN;
        Ws[j] = (kk < CIN) ? w[j] : 0.0f;
    }
    __syncthreads();

    int ty = tid >> 4, tx = tid & 15;
    u64 acc2[8][NP];
#pragma unroll
    for (int i = 0; i < 8; i++)
#pragma unroll
        for (int p = 0; p < NP; p++) acc2[i][p] = 0ULL;

#pragma unroll 8
    for (int kk = 0; kk < K1; kk++) {
        float4 a0 = *(const float4*)&As[kk * 132 + ty * 4];
        float4 a1 = *(const float4*)&As[kk * 132 + 64 + ty * 4];
        float ar[8] = {a0.x, a0.y, a0.z, a0.w, a1.x, a1.y, a1.z, a1.w};
        ulonglong2 b0 = *(const ulonglong2*)&Ws[kk * BN + tx * 4];
        ulonglong2 b1;
        if (NCF == 2) b1 = *(const ulonglong2*)&Ws[kk * BN + 64 + tx * 4];
#pragma unroll
        for (int i = 0; i < 8; i++) {
            u64 ad = pack2(ar[i]);
            fma2(acc2[i][0], ad, b0.x);
            fma2(acc2[i][1], ad, b0.y);
            if (NCF == 2) {
                fma2(acc2[i][2], ad, b1.x);
                fma2(acc2[i][3], ad, b1.y);
            }
        }
    }

    float acc[8][NCF * 4];
#pragma unroll
    for (int i = 0; i < 8; i++)
#pragma unroll
        for (int p = 0; p < NP; p++) {
            float2 f = unpack2(acc2[i][p]);
            acc[i][2 * p + 0] = f.x;
            acc[i][2 * p + 1] = f.y;
        }

#pragma unroll
    for (int cf = 0; cf < NCF; cf++) {
        float4 bb = *(const float4*)(bias + cf * 64 + tx * 4);
#pragma unroll
        for (int i = 0; i < 8; i++) {
            int m = m0 + (i < 4 ? ty * 4 + i : 64 + ty * 4 + i - 4);
            float4 o;
            o.x = acc[i][cf * 4 + 0] + bb.x;
            o.y = acc[i][cf * 4 + 1] + bb.y;
            o.z = acc[i][cf * 4 + 2] + bb.z;
            o.w = acc[i][cf * 4 + 3] + bb.w;
            acc[i][cf * 4 + 0] = o.x; acc[i][cf * 4 + 1] = o.y;
            acc[i][cf * 4 + 2] = o.z; acc[i][cf * 4 + 3] = o.w;
            *(float4*)(z1 + (size_t)m * BN + cf * 64 + tx * 4) = o;
        }
    }

    float* red = As;   // 5280 >= 16*BN
    __syncthreads();
#pragma unroll
    for (int cf = 0; cf < NCF; cf++)
#pragma unroll
        for (int j = 0; j < 4; j++) {
            float s = 0.0f;
#pragma unroll
            for (int i = 0; i < 8; i++) s += acc[i][cf * 4 + j];
            red[ty * BN + cf * 64 + tx * 4 + j] = s;
        }
    __syncthreads();
    if (tid < BN) {
        float s = 0.0f;
        for (int t = 0; t < 16; t++) s += red[t * BN + tid];
        partS[(size_t)by * BN + tid] = s;
    }
    __syncthreads();
#pragma unroll
    for (int cf = 0; cf < NCF; cf++)
#pragma unroll
        for (int j = 0; j < 4; j++) {
            float s = 0.0f;
#pragma unroll
            for (int i = 0; i < 8; i++) {
                float v = acc[i][cf * 4 + j];
                s += v * v;
            }
            red[ty * BN + cf * 64 + tx * 4 + j] = s;
        }
    __syncthreads();
    if (tid < BN) {
        float s = 0.0f;
        for (int t = 0; t < 16; t++) s += red[t * BN + tid];
        partQ[(size_t)by * BN + tid] = s;
    }
}

// ---------------- GEMM2: f32x2 with A pre-duplicated in smem (no per-MAC pack) ----------------
// grid (N/128, M/128), 256 threads. BM=128, BN=128, BK=8, double-buffered.
// As stores each A scalar duplicated into a u64 pair: pack once at staging.
#define LDTA 264
__global__ void __launch_bounds__(256)
gemm2_kernel(const float* __restrict__ A,     // M x K (z1, pre-BN)
             const float* __restrict__ W,     // K x N
             const float* __restrict__ bias,  // N
             const float* __restrict__ ab,    // [K] scale, [256+K] shift
             int M, int K, int N, int Kg,
             float* __restrict__ partS,
             float* __restrict__ partQ,
             float* __restrict__ gmax,
             float* __restrict__ gmin)
{
    __shared__ float As[2][8 * LDTA];        // duplicated pairs: 16.9 KB
    __shared__ float Ws[2][8 * 128];
    __shared__ float red[16 * 128];
    __shared__ float sA[128], sC[128];

    int tid = threadIdx.x;
    int m0  = blockIdx.y * 128;
    int n0  = blockIdx.x * 128;

    if (tid < K) { sA[tid] = ab[tid]; sC[tid] = ab[256 + tid]; }
    __syncthreads();

    int arow = tid >> 1, akc = (tid & 1) * 4;
    int wrow = tid >> 5, wnc = (tid & 31) * 4;
    int ty = tid >> 4, tx = tid & 15;

    const float* Ap = A + (size_t)(m0 + arow) * K + akc;
    const float* Wp = W + (size_t)wrow * N + n0 + wnc;

    // prologue: tile 0 (pack A once at store)
    {
        float4 av = *(const float4*)Ap;
        av.x = fmaxf(0.0f, fmaf(sA[akc + 0], av.x, sC[akc + 0]));
        av.y = fmaxf(0.0f, fmaf(sA[akc + 1], av.y, sC[akc + 1]));
        av.z = fmaxf(0.0f, fmaf(sA[akc + 2], av.z, sC[akc + 2]));
        av.w = fmaxf(0.0f, fmaf(sA[akc + 3], av.w, sC[akc + 3]));
        float4 wv = *(const float4*)Wp;
        *(u64*)&As[0][(akc + 0) * LDTA + 2 * arow] = pack2(av.x);
        *(u64*)&As[0][(akc + 1) * LDTA + 2 * arow] = pack2(av.y);
        *(u64*)&As[0][(akc + 2) * LDTA + 2 * arow] = pack2(av.z);
        *(u64*)&As[0][(akc + 3) * LDTA + 2 * arow] = pack2(av.w);
        *(float4*)&Ws[0][wrow * 128 + wnc] = wv;
    }
    __syncthreads();

    u64 acc2[8][4];
#pragma unroll
    for (int i = 0; i < 8; i++)
#pragma unroll
        for (int p = 0; p < 4; p++) acc2[i][p] = 0ULL;

    int buf = 0;
    for (int k0 = 0; k0 < K; k0 += 8) {
        bool more = (k0 + 8) < K;
        float4 an, wn;
        if (more) {
            an = *(const float4*)(Ap + k0 + 8);
            int kb = k0 + 8 + akc;
            an.x = fmaxf(0.0f, fmaf(sA[kb + 0], an.x, sC[kb + 0]));
            an.y = fmaxf(0.0f, fmaf(sA[kb + 1], an.y, sC[kb + 1]));
            an.z = fmaxf(0.0f, fmaf(sA[kb + 2], an.z, sC[kb + 2]));
            an.w = fmaxf(0.0f, fmaf(sA[kb + 3], an.w, sC[kb + 3]));
            wn = *(const float4*)(Wp + (size_t)(k0 + 8) * N);
        }
#pragma unroll
        for (int kk = 0; kk < 8; kk++) {
            ulonglong2 aA0 = *(const ulonglong2*)&As[buf][kk * LDTA + 8 * ty];
            ulonglong2 aA1 = *(const ulonglong2*)&As[buf][kk * LDTA + 8 * ty + 4];
            ulonglong2 aB0 = *(const ulonglong2*)&As[buf][kk * LDTA + 128 + 8 * ty];
            ulonglong2 aB1 = *(const ulonglong2*)&As[buf][kk * LDTA + 128 + 8 * ty + 4];
            ulonglong2 b0 = *(const ulonglong2*)&Ws[buf][kk * 128 + tx * 4];
            ulonglong2 b1 = *(const ulonglong2*)&Ws[buf][kk * 128 + 64 + tx * 4];
            u64 ar[8] = {aA0.x, aA0.y, aA1.x, aA1.y, aB0.x, aB0.y, aB1.x, aB1.y};
#pragma unroll
            for (int i = 0; i < 8; i++) {
                fma2(acc2[i][0], ar[i], b0.x);
                fma2(acc2[i][1], ar[i], b0.y);
                fma2(acc2[i][2], ar[i], b1.x);
                fma2(acc2[i][3], ar[i], b1.y);
            }
        }
        if (more) {
            int nb = buf ^ 1;
            *(u64*)&As[nb][(akc + 0) * LDTA + 2 * arow] = pack2(an.x);
            *(u64*)&As[nb][(akc + 1) * LDTA + 2 * arow] = pack2(an.y);
            *(u64*)&As[nb][(akc + 2) * LDTA + 2 * arow] = pack2(an.z);
            *(u64*)&As[nb][(akc + 3) * LDTA + 2 * arow] = pack2(an.w);
            *(float4*)&Ws[nb][wrow * 128 + wnc] = wn;
            __syncthreads();
            buf = nb;
        }
    }

    // unpack + bias (bit-identical to scalar path)
    float acc[8][8];
#pragma unroll
    for (int i = 0; i < 8; i++)
#pragma unroll
        for (int p = 0; p < 4; p++) {
            float2 f = unpack2(acc2[i][p]);
            acc[i][2 * p + 0] = f.x;
            acc[i][2 * p + 1] = f.y;
        }
#pragma unroll
    for (int cf = 0; cf < 2; cf++) {
        float4 bb = *(const float4*)(bias + n0 + cf * 64 + tx * 4);
#pragma unroll
        for (int i = 0; i < 8; i++) {
            acc[i][cf * 4 + 0] += bb.x;
            acc[i][cf * 4 + 1] += bb.y;
            acc[i][cf * 4 + 2] += bb.z;
            acc[i][cf * 4 + 3] += bb.w;
        }
    }

    int by = blockIdx.y;

    // ---- partial BN stats ----
    __syncthreads();
#pragma unroll
    for (int cf = 0; cf < 2; cf++)
#pragma unroll
        for (int j = 0; j < 4; j++) {
            float s = 0.0f;
#pragma unroll
            for (int i = 0; i < 8; i++) s += acc[i][cf * 4 + j];
            red[ty * 128 + cf * 64 + tx * 4 + j] = s;
        }
    __syncthreads();
    if (tid < 128) {
        float s = 0.0f;
        for (int t = 0; t < 16; t++) s += red[t * 128 + tid];
        partS[(size_t)by * N + n0 + tid] = s;
    }
    __syncthreads();
#pragma unroll
    for (int cf = 0; cf < 2; cf++)
#pragma unroll
        for (int j = 0; j < 4; j++) {
            float s = 0.0f;
#pragma unroll
            for (int i = 0; i < 8; i++) {
                float v = acc[i][cf * 4 + j];
                s += v * v;
            }
            red[ty * 128 + cf * 64 + tx * 4 + j] = s;
        }
    __syncthreads();
    if (tid < 128) {
        float s = 0.0f;
        for (int t = 0; t < 16; t++) s += red[t * 128 + tid];
        partQ[(size_t)by * N + n0 + tid] = s;
    }

    // ---- per-group max/min over the Kg-row pooling groups ----
    int gph = 64 / Kg;          // groups per 64-row half
    int typ = Kg / 4;           // ty's per group
#pragma unroll
    for (int h = 0; h < 2; h++) {
        __syncthreads();
#pragma unroll
        for (int cf = 0; cf < 2; cf++)
#pragma unroll
            for (int j = 0; j < 4; j++) {
                int q = cf * 4 + j, i0 = h * 4;
                float v = fmaxf(fmaxf(acc[i0][q], acc[i0 + 1][q]),
                                fmaxf(acc[i0 + 2][q], acc[i0 + 3][q]));
                red[ty * 128 + cf * 64 + tx * 4 + j] = v;
            }
        __syncthreads();
        if (tid < 128) {
            for (int g = 0; g < gph; g++) {
                float mx = -3.4e38f;
                for (int t = g * typ; t < (g + 1) * typ; t++)
                    mx = fmaxf(mx, red[t * 128 + tid]);
                int ggrp = (m0 + h * 64) / Kg + g;
                gmax[(size_t)ggrp * N + n0 + tid] = mx;
            }
        }
        __syncthreads();
#pragma unroll
        for (int cf = 0; cf < 2; cf++)
#pragma unroll
            for (int j = 0; j < 4; j++) {
                int q = cf * 4 + j, i0 = h * 4;
                float v = fminf(fminf(acc[i0][q], acc[i0 + 1][q]),
                                fminf(acc[i0 + 2][q], acc[i0 + 3][q]));
                red[ty * 128 + cf * 64 + tx * 4 + j] = v;
            }
        __syncthreads();
        if (tid < 128) {
            for (int g = 0; g < gph; g++) {
                float mn = 3.4e38f;
                for (int t = g * typ; t < (g + 1) * typ; t++)
                    mn = fminf(mn, red[t * 128 + tid]);
                int ggrp = (m0 + h * 64) / Kg + g;
                gmin[(size_t)ggrp * N + n0 + tid] = mn;
            }
        }
    }
}

// ---------------- final BN stats: one block per channel (measured-good config) ----------------
__global__ void stats_final(const float* __restrict__ partS,
                            const float* __restrict__ partQ,
                            int nby, int C, int Mtot,
                            const float* __restrict__ g,
                            const float* __restrict__ be,
                            float* __restrict__ ab)
{
    int c = blockIdx.x, t = threadIdx.x;
    double s = 0.0, q = 0.0;
    for (int i = t; i < nby; i += 256) {
        s += (double)partS[(size_t)i * C + c];
        q += (double)partQ[(size_t)i * C + c];
    }
    __shared__ double shS[256], shQ[256];
    shS[t] = s; shQ[t] = q;
    __syncthreads();
    for (int o = 128; o; o >>= 1) {
        if (t < o) { shS[t] += shS[t + o]; shQ[t] += shQ[t + o]; }
        __syncthreads();
    }
    if (t == 0) {
        double inv  = 1.0 / (double)Mtot;
        double mean = shS[0] * inv;
        double var  = shQ[0] * inv - mean * mean;
        float a = g[c] * rsqrtf((float)var + 1e-5f);
        ab[c]       = a;
        ab[256 + c] = be[c] - a * (float)mean;
    }
}

// ---------------- finisher: BN2 + ReLU on pooled extrema, transposed into d_out ----------------
__global__ void finish_kernel(const float* __restrict__ gmax,
                              const float* __restrict__ gmin,
                              const float* __restrict__ ab,
                              int C, int coff,
                              float* __restrict__ out)
{
    int bs = blockIdx.x;
    int c  = threadIdx.x;
    float a  = ab[c];
    float sh = ab[256 + c];
    float v  = (a >= 0.0f) ? gmax[(size_t)bs * C + c] : gmin[(size_t)bs * C + c];
    v = fmaxf(fmaf(a, v, sh), 0.0f);
    int b = bs >> 10, s = bs & 1023;
    out[(size_t)BATCH * NCEN * 3 + ((size_t)b * OUTCH + coff + c) * NCEN + s] = v;
}

// ---------------- launcher ----------------
extern "C" void kernel_launch(void* const* d_in, const int* in_sizes, int n_in,
                              void* d_out, int out_size)
{
    const float* xyz    = (const float*)d_in[0];
    const float* points = (const float*)d_in[1];
    auto P = [&](int sc, int ly, int k) { return (const float*)d_in[2 + (sc * 2 + ly) * 4 + k]; };

    float *z1, *part, *gmax, *gmin, *ab1, *ab2;
    int   *i0, *i1, *i2;
    cudaGetSymbolAddress((void**)&z1,   g_z1);
    cudaGetSymbolAddress((void**)&part, g_part);
    cudaGetSymbolAddress((void**)&gmax, g_gmax);
    cudaGetSymbolAddress((void**)&gmin, g_gmin);
    cudaGetSymbolAddress((void**)&ab1,  g_ab1);
    cudaGetSymbolAddress((void**)&ab2,  g_ab2);
    cudaGetSymbolAddress((void**)&i0,   g_idx0);
    cudaGetSymbolAddress((void**)&i1,   g_idx1);
    cudaGetSymbolAddress((void**)&i2,   g_idx2);
    float* partS = part;
    float* partQ = part + (size_t)4096 * 256;

    float* out    = (float*)d_out;
    float* newxyz = out;

    const int  Ks[3]   = {16, 32, 64};
    const int  C1s[3]  = {64, 128, 128};
    const int  C2s[3]  = {128, 256, 256};
    const int  coff[3] = {0, 128, 384};
    int* const idxs[3] = {i0, i1, i2};

    fps_kernel<<<BATCH, 512>>>(xyz, newxyz);
    ballquery_kernel<<<BATCH * 32, 128>>>(xyz, newxyz, i0, i1, i2);

    for (int si = 0; si < 3; si++) {
        int s  = 2 - si;                        // biggest scale first
        int K  = Ks[s];
        int C1 = C1s[s];
        int C2 = C2s[s];
        int M  = BATCH * NCEN * K;
        int nby = M / 128;

        if (C1 == 64)
            gemm1_kernel<64><<<nby, 256>>>(xyz, points, idxs[s], newxyz,
                                           P(s, 0, 0), P(s, 0, 1), K, z1, partS, partQ);
        else
            gemm1_kernel<128><<<nby, 256>>>(xyz, points, idxs[s], newxyz,
                                            P(s, 0, 0), P(s, 0, 1), K, z1, partS, partQ);
        stats_final<<<C1, 256>>>(partS, partQ, nby, C1, M, P(s, 0, 2), P(s, 0, 3), ab1);

        gemm2_kernel<<<dim3(C2 / 128, nby), 256>>>(z1, P(s, 1, 0), P(s, 1, 1), ab1,
                                                   M, C1, C2, K, partS, partQ, gmax, gmin);
        stats_final<<<C2, 256>>>(partS, partQ, nby, C2, M, P(s, 1, 2), P(s, 1, 3), ab2);

        finish_kernel<<<BATCH * NCEN, C2>>>(gmax, gmin, ab2, C2, coff[s], out);
    }
}

// round 16
// speedup vs baseline: 1.2406x; 1.2406x over previous
#include <cuda_runtime.h>

// ---------------- problem constants ----------------
#define BATCH   8
#define NPTS    4096
#define NCEN    1024
#define DFEAT   32
#define CIN     35        // 3 + D
#define K1      40        // padded K for layer-1 GEMM
#define OUTCH   640

typedef unsigned long long u64;

// ---------------- device scratch (no allocations allowed) ----------------
static __device__ float g_z1  [524288 * 128];       // 268 MB
static __device__ float g_part[2 * 4096 * 256];     // per-blockrow partial sums / sumsq
static __device__ float g_gmax[8192 * 256];         // per-(center,channel) group max
static __device__ float g_gmin[8192 * 256];         // per-(center,channel) group min
static __device__ float g_ab1 [512];
static __device__ float g_ab2 [512];
static __device__ int   g_idx0[BATCH * NCEN * 16];
static __device__ int   g_idx1[BATCH * NCEN * 32];
static __device__ int   g_idx2[BATCH * NCEN * 64];

// ---------------- packed f32x2 helpers ----------------
__device__ __forceinline__ u64 pack2(float x) {
    u64 d;
    asm("mov.b64 %0, {%1, %1};" : "=l"(d) : "f"(x));
    return d;
}
__device__ __forceinline__ void fma2(u64& c, u64 a, u64 b) {
    asm("fma.rn.f32x2 %0, %1, %2, %0;" : "+l"(c) : "l"(a), "l"(b));
}
__device__ __forceinline__ float2 unpack2(u64 d) {
    float2 f;
    asm("mov.b64 {%0, %1}, %2;" : "=f"(f.x), "=f"(f.y) : "l"(d));
    return f;
}

// ---------------- FPS: 512 threads, HW warp reductions, 1 bar/iter ----------------
__global__ void fps_kernel(const float* __restrict__ xyz, float* __restrict__ newxyz)
{
    int b   = blockIdx.x;
    int tid = threadIdx.x;                    // 512 threads
    const float* base = xyz + (size_t)b * NPTS * 3;

    float px[8], py[8], pz[8], dist[8];
#pragma unroll
    for (int u = 0; u < 8; u++) {
        int p = tid + u * 512;
        px[u] = base[p * 3 + 0];
        py[u] = base[p * 3 + 1];
        pz[u] = base[p * 3 + 2];
        dist[u] = 1e10f;
    }

    __shared__ unsigned s_vb[2][16];
    __shared__ unsigned s_ib[2][16];
    int lane = tid & 31, warp = tid >> 5;
    int far = 0;

    for (int t = 0; t < NCEN; t++) {
        float cx = base[far * 3 + 0];
        float cy = base[far * 3 + 1];
        float cz = base[far * 3 + 2];
        if (tid == 0) {
            float* o = newxyz + ((size_t)b * NCEN + t) * 3;
            o[0] = cx; o[1] = cy; o[2] = cz;
        }
        float bv = -1.0f; int bi = 0x7fffffff;
#pragma unroll
        for (int u = 0; u < 8; u++) {
            float dx = px[u] - cx, dy = py[u] - cy, dz = pz[u] - cz;
            float d  = dx * dx + dy * dy + dz * dz;
            float nd = fminf(dist[u], d);
            dist[u] = nd;
            int p = tid + u * 512;
            if (nd > bv || (nd == bv && p < bi)) { bv = nd; bi = p; }
        }
        // bv >= 0 always, so float bits compare as u32.
        int pb = t & 1;
        unsigned kb = __float_as_uint(bv);
        unsigned mx = __reduce_max_sync(0xffffffffu, kb);
        unsigned mi = __reduce_min_sync(0xffffffffu, (kb == mx) ? (unsigned)bi : 0xffffffffu);
        if (lane == 0) { s_vb[pb][warp] = mx; s_ib[pb][warp] = mi; }
        __syncthreads();
        // every warp redundantly reduces the 16 partials (no second barrier)
        unsigned v  = (lane < 16) ? s_vb[pb][lane] : 0u;
        unsigned ii = (lane < 16) ? s_ib[pb][lane] : 0xffffffffu;
        unsigned m2 = __reduce_max_sync(0xffffffffu, v);
        unsigned i2 = __reduce_min_sync(0xffffffffu, (v == m2) ? ii : 0xffffffffu);
        far = (int)i2;
    }
}

// ---------------- ball query: all 3 radii in one pass ----------------
__global__ void ballquery_kernel(const float* __restrict__ xyz,
                                 const float* __restrict__ newxyz,
                                 int* __restrict__ idx0,
                                 int* __restrict__ idx1,
                                 int* __restrict__ idx2)
{
    __shared__ float sx[NPTS], sy[NPTS], sz[NPTS];
    int b     = blockIdx.x >> 5;
    int cbase = (blockIdx.x & 31) * 32;
    const float* base = xyz + (size_t)b * NPTS * 3;

    for (int i = threadIdx.x; i < NPTS; i += 128) {
        sx[i] = base[i * 3 + 0];
        sy[i] = base[i * 3 + 1];
        sz[i] = base[i * 3 + 2];
    }
    __syncthreads();

    const float R0 = (float)(0.1 * 0.1);
    const float R1 = (float)(0.2 * 0.2);
    const float R2 = (float)(0.4 * 0.4);

    int warp = threadIdx.x >> 5, lane = threadIdx.x & 31;
    unsigned lmask = (1u << lane) - 1u;

    for (int ci = 0; ci < 8; ci++) {
        int s = cbase + warp * 8 + ci;
        const float* cen = newxyz + ((size_t)b * NCEN + s) * 3;
        float cx = cen[0], cy = cen[1], cz = cen[2];
        float cs2 = cx * cx + cy * cy + cz * cz;

        int n0 = 0, n1 = 0, n2 = 0;
        int f0 = 0, f1 = 0, f2 = 0;
        int* o0 = idx0 + ((size_t)b * NCEN + s) * 16;
        int* o1 = idx1 + ((size_t)b * NCEN + s) * 32;
        int* o2 = idx2 + ((size_t)b * NCEN + s) * 64;

        for (int bp = 0; bp < NPTS; bp += 32) {
            int p = bp + lane;
            float x = sx[p], y = sy[p], z = sz[p];
            float p2  = x * x + y * y + z * z;
            float dot = cx * x + cy * y + cz * z;
            float d   = (cs2 + p2) - 2.0f * dot;

            bool i2 = d <= R2;
            bool i1 = d <= R1;
            bool i0 = d <= R0;
            unsigned m0 = __ballot_sync(0xffffffffu, i0);
            unsigned m1 = __ballot_sync(0xffffffffu, i1);
            unsigned m2 = __ballot_sync(0xffffffffu, i2);

            if (n0 < 16) {
                if (i0) { int pos = n0 + __popc(m0 & lmask); if (pos < 16) o0[pos] = p; }
                if (n0 == 0 && m0) f0 = bp + __ffs(m0) - 1;
                n0 = min(16, n0 + __popc(m0));
            }
            if (n1 < 32) {
                if (i1) { int pos = n1 + __popc(m1 & lmask); if (pos < 32) o1[pos] = p; }
                if (n1 == 0 && m1) f1 = bp + __ffs(m1) - 1;
                n1 = min(32, n1 + __popc(m1));
            }
            if (n2 < 64) {
                if (i2) { int pos = n2 + __popc(m2 & lmask); if (pos < 64) o2[pos] = p; }
                if (n2 == 0 && m2) f2 = bp + __ffs(m2) - 1;
                n2 = min(64, n2 + __popc(m2));
            }
            if (n0 == 16 && n1 == 32 && n2 == 64) break;
        }
        for (int i = n0 + lane; i < 16; i += 32) o0[i] = f0;
        for (int i = n1 + lane; i < 32; i += 32) o1[i] = f1;
        for (int i = n2 + lane; i < 64; i += 32) o2[i] = f2;
    }
}

// ---------------- GEMM1: fused gather + (feat @ W1 + b1) + partial BN stats, f32x2 ----------------
template <int BN>
__global__ void __launch_bounds__(256)
gemm1_kernel(const float* __restrict__ xyz,
             const float* __restrict__ points,
             const int*   __restrict__ idx,
             const float* __restrict__ newxyz,
             const float* __restrict__ w,     // 35 x BN
             const float* __restrict__ bias,  // BN
             int Ksz,
             float* __restrict__ z1,          // M x BN
             float* __restrict__ partS,
             float* __restrict__ partQ)
{
    constexpr int NCF = BN / 64;
    constexpr int NP  = NCF * 2;
    __shared__ float As[K1 * 132];           // 5280 floats
    __shared__ float Ws[K1 * BN];

    int tid  = threadIdx.x;
    int by   = blockIdx.x;
    int m0   = by * 128;
    int warp = tid >> 5, lane = tid & 31;

    for (int r = warp; r < 128; r += 8) {
        int m  = m0 + r;
        int i  = idx[m];
        int bs = m / Ksz;
        int b  = bs >> 10;
        const float* px = xyz    + ((size_t)b * NPTS + i) * 3;
        const float* pf = points + ((size_t)b * NPTS + i) * DFEAT;
        const float* cn = newxyz + (size_t)bs * 3;
        float v = (lane < 3) ? (px[lane] - cn[lane]) : pf[lane - 3];
        As[lane * 132 + r] = v;
        if (lane < 8) {
            int k2 = lane + 32;
            As[k2 * 132 + r] = (k2 < CIN) ? pf[k2 - 3] : 0.0f;
        }
    }
    for (int j = tid; j < K1 * BN; j += 256) {
        int kk = j / BN;
        Ws[j] = (kk < CIN) ? w[j] : 0.0f;
    }
    __syncthreads();

    int ty = tid >> 4, tx = tid & 15;
    u64 acc2[8][NP];
#pragma unroll
    for (int i = 0; i < 8; i++)
#pragma unroll
        for (int p = 0; p < NP; p++) acc2[i][p] = 0ULL;

#pragma unroll 8
    for (int kk = 0; kk < K1; kk++) {
        float4 a0 = *(const float4*)&As[kk * 132 + ty * 4];
        float4 a1 = *(const float4*)&As[kk * 132 + 64 + ty * 4];
        float ar[8] = {a0.x, a0.y, a0.z, a0.w, a1.x, a1.y, a1.z, a1.w};
        ulonglong2 b0 = *(const ulonglong2*)&Ws[kk * BN + tx * 4];
        ulonglong2 b1;
        if (NCF == 2) b1 = *(const ulonglong2*)&Ws[kk * BN + 64 + tx * 4];
#pragma unroll
        for (int i = 0; i < 8; i++) {
            u64 ad = pack2(ar[i]);
            fma2(acc2[i][0], ad, b0.x);
            fma2(acc2[i][1], ad, b0.y);
            if (NCF == 2) {
                fma2(acc2[i][2], ad, b1.x);
                fma2(acc2[i][3], ad, b1.y);
            }
        }
    }

    float acc[8][NCF * 4];
#pragma unroll
    for (int i = 0; i < 8; i++)
#pragma unroll
        for (int p = 0; p < NP; p++) {
            float2 f = unpack2(acc2[i][p]);
            acc[i][2 * p + 0] = f.x;
            acc[i][2 * p + 1] = f.y;
        }

#pragma unroll
    for (int cf = 0; cf < NCF; cf++) {
        float4 bb = *(const float4*)(bias + cf * 64 + tx * 4);
#pragma unroll
        for (int i = 0; i < 8; i++) {
            int m = m0 + (i < 4 ? ty * 4 + i : 64 + ty * 4 + i - 4);
            float4 o;
            o.x = acc[i][cf * 4 + 0] + bb.x;
            o.y = acc[i][cf * 4 + 1] + bb.y;
            o.z = acc[i][cf * 4 + 2] + bb.z;
            o.w = acc[i][cf * 4 + 3] + bb.w;
            acc[i][cf * 4 + 0] = o.x; acc[i][cf * 4 + 1] = o.y;
            acc[i][cf * 4 + 2] = o.z; acc[i][cf * 4 + 3] = o.w;
            *(float4*)(z1 + (size_t)m * BN + cf * 64 + tx * 4) = o;
        }
    }

    float* red = As;   // 5280 >= 16*BN
    __syncthreads();
#pragma unroll
    for (int cf = 0; cf < NCF; cf++)
#pragma unroll
        for (int j = 0; j < 4; j++) {
            float s = 0.0f;
#pragma unroll
            for (int i = 0; i < 8; i++) s += acc[i][cf * 4 + j];
            red[ty * BN + cf * 64 + tx * 4 + j] = s;
        }
    __syncthreads();
    if (tid < BN) {
        float s = 0.0f;
        for (int t = 0; t < 16; t++) s += red[t * BN + tid];
        partS[(size_t)by * BN + tid] = s;
    }
    __syncthreads();
#pragma unroll
    for (int cf = 0; cf < NCF; cf++)
#pragma unroll
        for (int j = 0; j < 4; j++) {
            float s = 0.0f;
#pragma unroll
            for (int i = 0; i < 8; i++) {
                float v = acc[i][cf * 4 + j];
                s += v * v;
            }
            red[ty * BN + cf * 64 + tx * 4 + j] = s;
        }
    __syncthreads();
    if (tid < BN) {
        float s = 0.0f;
        for (int t = 0; t < 16; t++) s += red[t * BN + tid];
        partQ[(size_t)by * BN + tid] = s;
    }
}

// ---------------- GEMM2: relu(bn(z1)) @ W2 + b2, f32x2, BK=8 (measured best, round-14 form) ----------------
// grid (N/128, M/128), 256 threads. BM=128, BN=128, BK=8, double-buffered.
__global__ void __launch_bounds__(256)
gemm2_kernel(const float* __restrict__ A,     // M x K (z1, pre-BN)
             const float* __restrict__ W,     // K x N
             const float* __restrict__ bias,  // N
             const float* __restrict__ ab,    // [K] scale, [256+K] shift
             int M, int K, int N, int Kg,
             float* __restrict__ partS,
             float* __restrict__ partQ,
             float* __restrict__ gmax,
             float* __restrict__ gmin)
{
    __shared__ float As[2][8 * 132];
    __shared__ float Ws[2][8 * 128];
    __shared__ float red[16 * 128];
    __shared__ float sA[128], sC[128];

    int tid = threadIdx.x;
    int m0  = blockIdx.y * 128;
    int n0  = blockIdx.x * 128;

    if (tid < K) { sA[tid] = ab[tid]; sC[tid] = ab[256 + tid]; }
    __syncthreads();

    int arow = tid >> 1, akc = (tid & 1) * 4;
    int wrow = tid >> 5, wnc = (tid & 31) * 4;
    int ty = tid >> 4, tx = tid & 15;

    const float* Ap = A + (size_t)(m0 + arow) * K + akc;
    const float* Wp = W + (size_t)wrow * N + n0 + wnc;

    // prologue: tile 0
    float4 av = *(const float4*)Ap;
    av.x = fmaxf(0.0f, fmaf(sA[akc + 0], av.x, sC[akc + 0]));
    av.y = fmaxf(0.0f, fmaf(sA[akc + 1], av.y, sC[akc + 1]));
    av.z = fmaxf(0.0f, fmaf(sA[akc + 2], av.z, sC[akc + 2]));
    av.w = fmaxf(0.0f, fmaf(sA[akc + 3], av.w, sC[akc + 3]));
    float4 wv = *(const float4*)Wp;
    As[0][(akc + 0) * 132 + arow] = av.x;
    As[0][(akc + 1) * 132 + arow] = av.y;
    As[0][(akc + 2) * 132 + arow] = av.z;
    As[0][(akc + 3) * 132 + arow] = av.w;
    *(float4*)&Ws[0][wrow * 128 + wnc] = wv;
    __syncthreads();

    u64 acc2[8][4];
#pragma unroll
    for (int i = 0; i < 8; i++)
#pragma unroll
        for (int p = 0; p < 4; p++) acc2[i][p] = 0ULL;

    int buf = 0;
    for (int k0 = 0; k0 < K; k0 += 8) {
        bool more = (k0 + 8) < K;
        float4 an, wn;
        if (more) {
            an = *(const float4*)(Ap + k0 + 8);
            int kb = k0 + 8 + akc;
            an.x = fmaxf(0.0f, fmaf(sA[kb + 0], an.x, sC[kb + 0]));
            an.y = fmaxf(0.0f, fmaf(sA[kb + 1], an.y, sC[kb + 1]));
            an.z = fmaxf(0.0f, fmaf(sA[kb + 2], an.z, sC[kb + 2]));
            an.w = fmaxf(0.0f, fmaf(sA[kb + 3], an.w, sC[kb + 3]));
            wn = *(const float4*)(Wp + (size_t)(k0 + 8) * N);
        }
#pragma unroll
        for (int kk = 0; kk < 8; kk++) {
            float4 a0 = *(const float4*)&As[buf][kk * 132 + ty * 4];
            float4 a1 = *(const float4*)&As[buf][kk * 132 + 64 + ty * 4];
            ulonglong2 b0 = *(const ulonglong2*)&Ws[buf][kk * 128 + tx * 4];
            ulonglong2 b1 = *(const ulonglong2*)&Ws[buf][kk * 128 + 64 + tx * 4];
            float ar[8] = {a0.x, a0.y, a0.z, a0.w, a1.x, a1.y, a1.z, a1.w};
#pragma unroll
            for (int i = 0; i < 8; i++) {
                u64 ad = pack2(ar[i]);
                fma2(acc2[i][0], ad, b0.x);
                fma2(acc2[i][1], ad, b0.y);
                fma2(acc2[i][2], ad, b1.x);
                fma2(acc2[i][3], ad, b1.y);
            }
        }
        if (more) {
            int nb = buf ^ 1;
            As[nb][(akc + 0) * 132 + arow] = an.x;
            As[nb][(akc + 1) * 132 + arow] = an.y;
            As[nb][(akc + 2) * 132 + arow] = an.z;
            As[nb][(akc + 3) * 132 + arow] = an.w;
            *(float4*)&Ws[nb][wrow * 128 + wnc] = wn;
            __syncthreads();
            buf = nb;
        }
    }

    // unpack + bias (bit-identical to scalar path)
    float acc[8][8];
#pragma unroll
    for (int i = 0; i < 8; i++)
#pragma unroll
        for (int p = 0; p < 4; p++) {
            float2 f = unpack2(acc2[i][p]);
            acc[i][2 * p + 0] = f.x;
            acc[i][2 * p + 1] = f.y;
        }
#pragma unroll
    for (int cf = 0; cf < 2; cf++) {
        float4 bb = *(const float4*)(bias + n0 + cf * 64 + tx * 4);
#pragma unroll
        for (int i = 0; i < 8; i++) {
            acc[i][cf * 4 + 0] += bb.x;
            acc[i][cf * 4 + 1] += bb.y;
            acc[i][cf * 4 + 2] += bb.z;
            acc[i][cf * 4 + 3] += bb.w;
        }
    }

    int by = blockIdx.y;

    // ---- partial BN stats ----
    __syncthreads();
#pragma unroll
    for (int cf = 0; cf < 2; cf++)
#pragma unroll
        for (int j = 0; j < 4; j++) {
            float s = 0.0f;
#pragma unroll
            for (int i = 0; i < 8; i++) s += acc[i][cf * 4 + j];
            red[ty * 128 + cf * 64 + tx * 4 + j] = s;
        }
    __syncthreads();
    if (tid < 128) {
        float s = 0.0f;
        for (int t = 0; t < 16; t++) s += red[t * 128 + tid];
        partS[(size_t)by * N + n0 + tid] = s;
    }
    __syncthreads();
#pragma unroll
    for (int cf = 0; cf < 2; cf++)
#pragma unroll
        for (int j = 0; j < 4; j++) {
            float s = 0.0f;
#pragma unroll
            for (int i = 0; i < 8; i++) {
                float v = acc[i][cf * 4 + j];
                s += v * v;
            }
            red[ty * 128 + cf * 64 + tx * 4 + j] = s;
        }
    __syncthreads();
    if (tid < 128) {
        float s = 0.0f;
        for (int t = 0; t < 16; t++) s += red[t * 128 + tid];
        partQ[(size_t)by * N + n0 + tid] = s;
    }

    // ---- per-group max/min over the Kg-row pooling groups ----
    int gph = 64 / Kg;          // groups per 64-row half
    int typ = Kg / 4;           // ty's per group
#pragma unroll
    for (int h = 0; h < 2; h++) {
        __syncthreads();
#pragma unroll
        for (int cf = 0; cf < 2; cf++)
#pragma unroll
            for (int j = 0; j < 4; j++) {
                int q = cf * 4 + j, i0 = h * 4;
                float v = fmaxf(fmaxf(acc[i0][q], acc[i0 + 1][q]),
                                fmaxf(acc[i0 + 2][q], acc[i0 + 3][q]));
                red[ty * 128 + cf * 64 + tx * 4 + j] = v;
            }
        __syncthreads();
        if (tid < 128) {
            for (int g = 0; g < gph; g++) {
                float mx = -3.4e38f;
                for (int t = g * typ; t < (g + 1) * typ; t++)
                    mx = fmaxf(mx, red[t * 128 + tid]);
                int ggrp = (m0 + h * 64) / Kg + g;
                gmax[(size_t)ggrp * N + n0 + tid] = mx;
            }
        }
        __syncthreads();
#pragma unroll
        for (int cf = 0; cf < 2; cf++)
#pragma unroll
            for (int j = 0; j < 4; j++) {
                int q = cf * 4 + j, i0 = h * 4;
                float v = fminf(fminf(acc[i0][q], acc[i0 + 1][q]),
                                fminf(acc[i0 + 2][q], acc[i0 + 3][q]));
                red[ty * 128 + cf * 64 + tx * 4 + j] = v;
            }
        __syncthreads();
        if (tid < 128) {
            for (int g = 0; g < gph; g++) {
                float mn = 3.4e38f;
                for (int t = g * typ; t < (g + 1) * typ; t++)
                    mn = fminf(mn, red[t * 128 + tid]);
                int ggrp = (m0 + h * 64) / Kg + g;
                gmin[(size_t)ggrp * N + n0 + tid] = mn;
            }
        }
    }
}

// ---------------- final BN stats: one block per channel (measured-good config) ----------------
__global__ void stats_final(const float* __restrict__ partS,
                            const float* __restrict__ partQ,
                            int nby, int C, int Mtot,
                            const float* __restrict__ g,
                            const float* __restrict__ be,
                            float* __restrict__ ab)
{
    int c = blockIdx.x, t = threadIdx.x;
    double s = 0.0, q = 0.0;
    for (int i = t; i < nby; i += 256) {
        s += (double)partS[(size_t)i * C + c];
        q += (double)partQ[(size_t)i * C + c];
    }
    __shared__ double shS[256], shQ[256];
    shS[t] = s; shQ[t] = q;
    __syncthreads();
    for (int o = 128; o; o >>= 1) {
        if (t < o) { shS[t] += shS[t + o]; shQ[t] += shQ[t + o]; }
        __syncthreads();
    }
    if (t == 0) {
        double inv  = 1.0 / (double)Mtot;
        double mean = shS[0] * inv;
        double var  = shQ[0] * inv - mean * mean;
        float a = g[c] * rsqrtf((float)var + 1e-5f);
        ab[c]       = a;
        ab[256 + c] = be[c] - a * (float)mean;
    }
}

// ---------------- finisher: BN2 + ReLU on pooled extrema, transposed into d_out ----------------
__global__ void finish_kernel(const float* __restrict__ gmax,
                              const float* __restrict__ gmin,
                              const float* __restrict__ ab,
                              int C, int coff,
                              float* __restrict__ out)
{
    int bs = blockIdx.x;
    int c  = threadIdx.x;
    float a  = ab[c];
    float sh = ab[256 + c];
    float v  = (a >= 0.0f) ? gmax[(size_t)bs * C + c] : gmin[(size_t)bs * C + c];
    v = fmaxf(fmaf(a, v, sh), 0.0f);
    int b = bs >> 10, s = bs & 1023;
    out[(size_t)BATCH * NCEN * 3 + ((size_t)b * OUTCH + coff + c) * NCEN + s] = v;
}

// ---------------- launcher ----------------
extern "C" void kernel_launch(void* const* d_in, const int* in_sizes, int n_in,
                              void* d_out, int out_size)
{
    const float* xyz    = (const float*)d_in[0];
    const float* points = (const float*)d_in[1];
    auto P = [&](int sc, int ly, int k) { return (const float*)d_in[2 + (sc * 2 + ly) * 4 + k]; };

    float *z1, *part, *gmax, *gmin, *ab1, *ab2;
    int   *i0, *i1, *i2;
    cudaGetSymbolAddress((void**)&z1,   g_z1);
    cudaGetSymbolAddress((void**)&part, g_part);
    cudaGetSymbolAddress((void**)&gmax, g_gmax);
    cudaGetSymbolAddress((void**)&gmin, g_gmin);
    cudaGetSymbolAddress((void**)&ab1,  g_ab1);
    cudaGetSymbolAddress((void**)&ab2,  g_ab2);
    cudaGetSymbolAddress((void**)&i0,   g_idx0);
    cudaGetSymbolAddress((void**)&i1,   g_idx1);
    cudaGetSymbolAddress((void**)&i2,   g_idx2);
    float* partS = part;
    float* partQ = part + (size_t)4096 * 256;

    float* out    = (float*)d_out;
    float* newxyz = out;

    const int  Ks[3]   = {16, 32, 64};
    const int  C1s[3]  = {64, 128, 128};
    const int  C2s[3]  = {128, 256, 256};
    const int  coff[3] = {0, 128, 384};
    int* const idxs[3] = {i0, i1, i2};

    fps_kernel<<<BATCH, 512>>>(xyz, newxyz);
    ballquery_kernel<<<BATCH * 32, 128>>>(xyz, newxyz, i0, i1, i2);

    for (int si = 0; si < 3; si++) {
        int s  = 2 - si;                        // biggest scale first
        int K  = Ks[s];
        int C1 = C1s[s];
        int C2 = C2s[s];
        int M  = BATCH * NCEN * K;
        int nby = M / 128;

        if (C1 == 64)
            gemm1_kernel<64><<<nby, 256>>>(xyz, points, idxs[s], newxyz,
                                           P(s, 0, 0), P(s, 0, 1), K, z1, partS, partQ);
        else
            gemm1_kernel<128><<<nby, 256>>>(xyz, points, idxs[s], newxyz,
                                            P(s, 0, 0), P(s, 0, 1), K, z1, partS, partQ);
        stats_final<<<C1, 256>>>(partS, partQ, nby, C1, M, P(s, 0, 2), P(s, 0, 3), ab1);

        gemm2_kernel<<<dim3(C2 / 128, nby), 256>>>(z1, P(s, 1, 0), P(s, 1, 1), ab1,
                                                   M, C1, C2, K, partS, partQ, gmax, gmin);
        stats_final<<<C2, 256>>>(partS, partQ, nby, C2, M, P(s, 1, 2), P(s, 1, 3), ab2);

        finish_kernel<<<BATCH * NCEN, C2>>>(gmax, gmin, ab2, C2, coff[s], out);
    }
}